// round 6
// baseline (speedup 1.0000x reference)
#include <cuda_runtime.h>
#include <cuda_bf16.h>

// GraphTrainNN: out[b] = prod_g  w2[g] * (w1[g]^2 + w0[g]*x[b,g]^2) / (w1[g]^2 + x[b,g]^2)
// B = 524288 rows, G = 127 genes. x: (B,G) fp32, w: (G,3) fp32 [w0, w1, w2].
//
// R6: persistent blocks + cp.async double-buffered smem staging, FINE GRAIN.
//  - 32-row tiles (16.25 KB), double buffered -> 32.5 KB smem/block ->
//    7 blocks/SM (grid 1036), warp occupancy ~85%.
//  - finer barrier quantum (~0.65us) + 7 independent staging streams per SM
//    smooths the DRAM request stream; tail imbalance ~0.2us.
//  - warp computes 4 rows: per-lane 4-gene ratio, 1 division/row, 5 butterfly
//    levels with 4 interleaved chains; float4 output store.

#define GG 127
#define RPT 32                         // rows per tile
#define FPT (RPT * GG)                 // floats per tile = 4064
#define F4PT (FPT / 4)                 // float4 per tile = 1016
#define TBYTES (FPT * 4)               // tile bytes = 16256
#define NBLOCKS (148 * 7)              // 1036 persistent blocks

__global__ __launch_bounds__(256, 7)
void hill_smem32_kernel(const float* __restrict__ x,
                        const float* __restrict__ w,
                        float* __restrict__ out,
                        int ntiles)
{
    extern __shared__ float sbuf[];    // 2 * FPT floats
    const int tid  = threadIdx.x;
    const int lane = tid & 31;
    const int wib  = tid >> 5;         // warp in block, 0..7

    // ---- per-lane gene parameters (loaded once) ----
    float w0c[4], wnc[4];
    float w2l = 1.0f;
#pragma unroll
    for (int j = 0; j < 4; ++j) {
        const int g = lane + 32 * j;
        if (g < GG) {
            const float a = __ldg(&w[g * 3 + 0]);
            const float k = __ldg(&w[g * 3 + 1]);
            const float s = __ldg(&w[g * 3 + 2]);
            w0c[j] = a;
            wnc[j] = k * k;
            w2l   *= s;
        } else {
            w0c[j] = 0.0f;   // identity gene: num term = den term = 1
            wnc[j] = 1.0f;
        }
    }
#pragma unroll
    for (int o = 16; o; o >>= 1)
        w2l *= __shfl_xor_sync(0xFFFFFFFFu, w2l, o);
    const float W2ALL = w2l;

    const unsigned smem_base = (unsigned)__cvta_generic_to_shared(sbuf);

    // ---- stage one 32-row tile via cp.async (16B, aligned, coalesced) ----
    auto stage = [&](int buf, int tile) {
        const float4* __restrict__ src =
            reinterpret_cast<const float4*>(x) + (size_t)tile * F4PT;
        const unsigned dst = smem_base + buf * TBYTES;
#pragma unroll
        for (int it = 0; it < 4; ++it) {
            const int idx = it * 256 + tid;
            if (idx < F4PT)
                asm volatile("cp.async.cg.shared.global [%0], [%1], 16;\n"
                             :: "r"(dst + idx * 16), "l"(src + idx));
        }
        asm volatile("cp.async.commit_group;\n" ::: "memory");
    };

    // ---- compute one tile: warp wib owns rows [wib*4, wib*4+4) ----
    auto compute = [&](int buf, int tile) {
        const float* __restrict__ s = sbuf + buf * FPT + wib * 4 * GG;

        float num[4], den[4];
#pragma unroll
        for (int r = 0; r < 4; ++r) { num[r] = 1.0f; den[r] = 1.0f; }

#pragma unroll
        for (int j = 0; j < 4; ++j) {
            const int g = lane + 32 * j;
#pragma unroll
            for (int r = 0; r < 4; ++r) {
                const float xv = (g < GG) ? s[r * GG + g] : 0.0f;
                const float a  = xv * xv;
                num[r] *= fmaf(w0c[j], a, wnc[j]);   // wn + w0*x^n
                den[r] *= (wnc[j] + a);              // wn + x^n
            }
        }

        float rr[4];
#pragma unroll
        for (int r = 0; r < 4; ++r)
            rr[r] = __fdividef(num[r], den[r]);      // in [~1e-4, 1]

#pragma unroll
        for (int o = 1; o <= 16; o <<= 1)
#pragma unroll
            for (int r = 0; r < 4; ++r)
                rr[r] *= __shfl_xor_sync(0xFFFFFFFFu, rr[r], o);

        if (lane == 0) {
            const int base = tile * RPT + wib * 4;   // multiple of 4
            float4 o4;
            o4.x = W2ALL * rr[0];
            o4.y = W2ALL * rr[1];
            o4.z = W2ALL * rr[2];
            o4.w = W2ALL * rr[3];
            *reinterpret_cast<float4*>(out + base) = o4;
        }
    };

    // ---- persistent double-buffered tile loop ----
    int t = blockIdx.x;
    if (t >= ntiles) return;
    stage(0, t);

    int buf = 0;
    for (int i = t; i < ntiles; i += gridDim.x, buf ^= 1) {
        const int nxt = i + gridDim.x;
        if (nxt < ntiles) {
            stage(buf ^ 1, nxt);                     // prefetch next tile
            asm volatile("cp.async.wait_group 1;\n" ::: "memory");
        } else {
            asm volatile("cp.async.wait_group 0;\n" ::: "memory");
        }
        __syncthreads();          // tile i visible to all warps
        compute(buf, i);
        __syncthreads();          // all reads done before buf is re-staged
    }
}

extern "C" void kernel_launch(void* const* d_in, const int* in_sizes, int n_in,
                              void* d_out, int out_size)
{
    const float* x = (const float*)d_in[0];   // (B, G) fp32
    const float* w = (const float*)d_in[1];   // (G, 3) fp32
    float* out = (float*)d_out;               // (B, 1) fp32

    const int rows   = in_sizes[0] / GG;      // 524288
    const int ntiles = rows / RPT;            // 16384

    cudaFuncSetAttribute(hill_smem32_kernel,
                         cudaFuncAttributeMaxDynamicSharedMemorySize,
                         2 * TBYTES);

    hill_smem32_kernel<<<NBLOCKS, 256, 2 * TBYTES>>>(x, w, out, ntiles);
}

// round 7
// speedup vs baseline: 1.1910x; 1.1910x over previous
#include <cuda_runtime.h>
#include <cuda_bf16.h>

// GraphTrainNN: out[b] = prod_g  w2[g] * (w1[g]^2 + w0[g]*x[b,g]^2) / (w1[g]^2 + x[b,g]^2)
// B = 524288 rows, G = 127 genes. x: (B,G) fp32, w: (G,3) fp32.
//
// R7: ALIGNED float4 streaming over 4-row groups (508 floats = 127 float4),
// software-pipelined (register ping-pong).
//  - warp loads float4 slots lane+32j (j=0..3; slot 127 unused) -> 4 aligned
//    LDG.128 per group (vs 16 misaligned LDG.32): -75% LDG count, -18% sectors.
//  - gene of element (slot,c) is (4*lane + j + c) mod 127  [128 == 1 mod 127],
//    so each lane needs only 7 (w0, w1^2) param pairs, fixed across groups.
//  - only lane 31 straddles row boundaries (slots 31/63/95); fixed with selects.
//  - per-lane per-row ratio (num<=den scale, safe), 1 division per row,
//    5-level butterfly with 4 interleaved chains, float4 output store.

#define GG 127

__global__ __launch_bounds__(256, 4)
void hill_f4_kernel(const float* __restrict__ x,
                    const float* __restrict__ w,
                    float* __restrict__ out,
                    int ngroups)
{
    const int lane   = threadIdx.x & 31;
    const int warp   = (blockIdx.x * blockDim.x + threadIdx.x) >> 5;
    const int nwarps = (gridDim.x * blockDim.x) >> 5;

    // ---- per-lane params: genes (4*lane + k) mod 127, k = 0..6 ----
    float p0[7], pn[7];
#pragma unroll
    for (int k = 0; k < 7; ++k) {
        int gene = 4 * lane + k;
        if (gene >= GG) gene -= GG;
        p0[k] = __ldg(&w[gene * 3 + 0]);
        const float kk = __ldg(&w[gene * 3 + 1]);
        pn[k] = kk * kk;
    }
    // prod of w2 over all genes (each gene owned once: 4*lane+k, k<4, idx<127)
    float w2l = 1.0f;
#pragma unroll
    for (int k = 0; k < 4; ++k) {
        const int idx = 4 * lane + k;
        if (idx < GG) w2l *= __ldg(&w[idx * 3 + 2]);
    }
#pragma unroll
    for (int o = 16; o; o >>= 1)
        w2l *= __shfl_xor_sync(0xFFFFFFFFu, w2l, o);
    const float W2ALL = w2l;

    const bool l31 = (lane == 31);
    const float4* __restrict__ xg = reinterpret_cast<const float4*>(x);

    // ---- load one 4-row group (127 float4, slot 127 unused -> clamp) ----
    auto load4 = [&](float4 (&v)[4], int grp) {
        const size_t base = (size_t)grp * GG;   // in float4 units
#pragma unroll
        for (int j = 0; j < 4; ++j) {
            int slot = lane + 32 * j;
            if (slot > 126) slot = 126;         // lane31,j=3: dup, discarded
            v[j] = __ldg(xg + base + slot);
        }
    };

    // ---- compute one group ----
    auto compute4 = [&](const float4 (&v)[4], int grp) {
        // per-element hill terms; tn[j][c], td[j][c]
        float tn[4][4], td[4][4];
#pragma unroll
        for (int j = 0; j < 4; ++j) {
            const float e[4] = { v[j].x, v[j].y, v[j].z, v[j].w };
#pragma unroll
            for (int c = 0; c < 4; ++c) {
                const int k = j + c;
                const float a = e[c] * e[c];
                tn[j][c] = fmaf(p0[k], a, pn[k]);   // wn + w0*x^2
                td[j][c] = pn[k] + a;               // wn + x^2
            }
        }

        // assemble per-row partial products.
        // lanes 0..30: slot j entirely in row j.
        // lane 31: row0 = t[0][0..2]; row1 = t[0][3],t[1][0],t[1][1];
        //          row2 = t[1][2],t[1][3],t[2][0]; row3 = t[2][1..3].
        float num[4], den[4];
        {
            const float n00 = tn[0][0] * tn[0][1] * tn[0][2];
            const float d00 = td[0][0] * td[0][1] * td[0][2];
            num[0] = l31 ? n00 : n00 * tn[0][3];
            den[0] = l31 ? d00 : d00 * td[0][3];

            const float n1a = tn[1][0] * tn[1][1];
            const float d1a = td[1][0] * td[1][1];
            num[1] = l31 ? tn[0][3] * n1a : n1a * tn[1][2] * tn[1][3];
            den[1] = l31 ? td[0][3] * d1a : d1a * td[1][2] * td[1][3];

            const float n2a = tn[1][2] * tn[1][3];
            const float d2a = td[1][2] * td[1][3];
            const float n2b = tn[2][0] * tn[2][1] * tn[2][2];
            const float d2b = td[2][0] * td[2][1] * td[2][2];
            num[2] = l31 ? n2a * tn[2][0] : n2b * tn[2][3];
            den[2] = l31 ? d2a * td[2][0] : d2b * td[2][3];

            const float n3a = tn[2][1] * tn[2][2] * tn[2][3];
            const float d3a = td[2][1] * td[2][2] * td[2][3];
            const float n3b = tn[3][0] * tn[3][1] * tn[3][2] * tn[3][3];
            const float d3b = td[3][0] * td[3][1] * td[3][2] * td[3][3];
            num[3] = l31 ? n3a : n3b;
            den[3] = l31 ? d3a : d3b;
        }

        float rr[4];
#pragma unroll
        for (int r = 0; r < 4; ++r)
            rr[r] = __fdividef(num[r], den[r]);     // <= ~4 terms: safe range

#pragma unroll
        for (int o = 1; o <= 16; o <<= 1)
#pragma unroll
            for (int r = 0; r < 4; ++r)
                rr[r] *= __shfl_xor_sync(0xFFFFFFFFu, rr[r], o);

        if (lane == 0) {
            float4 o4;
            o4.x = W2ALL * rr[0];
            o4.y = W2ALL * rr[1];
            o4.z = W2ALL * rr[2];
            o4.w = W2ALL * rr[3];
            *reinterpret_cast<float4*>(out + grp * 4) = o4;
        }
    };

    // ---- pipelined group loop (ping-pong) ----
    int grp = warp;
    if (grp >= ngroups) return;

    float4 bufA[4], bufB[4];
    load4(bufA, grp);

    for (;;) {
        int nxt = grp + nwarps;
        if (nxt < ngroups) load4(bufB, nxt);     // prefetch while A computes
        compute4(bufA, grp);
        grp = nxt;
        if (grp >= ngroups) break;

        nxt = grp + nwarps;
        if (nxt < ngroups) load4(bufA, nxt);     // prefetch while B computes
        compute4(bufB, grp);
        grp = nxt;
        if (grp >= ngroups) break;
    }
}

extern "C" void kernel_launch(void* const* d_in, const int* in_sizes, int n_in,
                              void* d_out, int out_size)
{
    const float* x = (const float*)d_in[0];   // (B, G) fp32
    const float* w = (const float*)d_in[1];   // (G, 3) fp32
    float* out = (float*)d_out;               // (B, 1) fp32

    const int rows    = in_sizes[0] / GG;     // 524288
    const int ngroups = rows / 4;             // 131072

    const int threads = 256;
    const int blocks  = 2048;                 // 16384 warps, 8 groups each
    hill_f4_kernel<<<blocks, threads>>>(x, w, out, ngroups);
}

// round 8
// speedup vs baseline: 1.2574x; 1.0558x over previous
#include <cuda_runtime.h>
#include <cuda_bf16.h>

// GraphTrainNN: out[b] = prod_g  w2[g] * (w1[g]^2 + w0[g]*x[b,g]^2) / (w1[g]^2 + x[b,g]^2)
// B = 524288 rows, G = 127 genes. x: (B,G) fp32, w: (G,3) fp32.
//
// R8: aligned float4 streaming (4-row group = 508 floats = 127 float4) with a
// register-light LOW/HIGH split-product assembly.
//  - warp loads float4 slots lane+32j (j=0..3) -> 4 aligned LDG.128 per group,
//    512B contiguous per request (~16 sectors vs ~20 for misaligned scalar).
//  - gene of element (slot,c) = (4*lane + j + c) mod 127  [128 == 1 mod 127]
//    -> 7 fixed (w0, w1^2) pairs per lane.
//  - slot j's terms split at s_j into low/high partial products;
//    generic lanes: s={4,4,4,4}; lane 31 (row-straddling slots 31/63/95 and
//    clamped slot 127): s={3,2,1,0}. Uniform fold: num[r]=high[r-1]*low[r].
//  - 1 division per row, 5-level butterfly with 4 interleaved chains,
//    float4 output store. prod(w2) hoisted per warp.

#define GG 127

__global__ __launch_bounds__(256, 5)
void hill_f4s_kernel(const float* __restrict__ x,
                     const float* __restrict__ w,
                     float* __restrict__ out,
                     int ngroups)
{
    const int lane   = threadIdx.x & 31;
    const int warp   = (blockIdx.x * blockDim.x + threadIdx.x) >> 5;
    const int nwarps = (gridDim.x * blockDim.x) >> 5;
    const bool l31   = (lane == 31);

    // ---- per-lane params: genes (4*lane + k) mod 127, k = 0..6 ----
    float p0[7], pn[7];
#pragma unroll
    for (int k = 0; k < 7; ++k) {
        int gene = 4 * lane + k;
        if (gene >= GG) gene -= GG;
        p0[k] = __ldg(&w[gene * 3 + 0]);
        const float kk = __ldg(&w[gene * 3 + 1]);
        pn[k] = kk * kk;
    }
    // prod of w2 over all genes (lane owns genes 4*lane+k, k<4, idx<127)
    float w2l = 1.0f;
#pragma unroll
    for (int k = 0; k < 4; ++k) {
        const int idx = 4 * lane + k;
        if (idx < GG) w2l *= __ldg(&w[idx * 3 + 2]);
    }
#pragma unroll
    for (int o = 16; o; o >>= 1)
        w2l *= __shfl_xor_sync(0xFFFFFFFFu, w2l, o);
    const float W2ALL = w2l;

    const float4* __restrict__ xg = reinterpret_cast<const float4*>(x);

    for (int grp = warp; grp < ngroups; grp += nwarps) {
        // ---- 4 aligned vector loads (all independent, issued up front) ----
        float4 v[4];
        const size_t base = (size_t)grp * GG;   // float4 units
#pragma unroll
        for (int j = 0; j < 4; ++j) {
            int slot = lane + 32 * j;
            if (slot > 126) slot = 126;          // lane31 j=3: dup, discarded
            v[j] = __ldg(xg + base + slot);
        }

        // ---- low/high split products per slot, folded across rows ----
        float num[4], den[4];
        float hn = 1.0f, hd = 1.0f;              // carry from previous slot
#pragma unroll
        for (int j = 0; j < 4; ++j) {
            const int s = l31 ? (3 - j) : 4;     // split point for this slot
            float ln = 1.0f, ld = 1.0f;          // low part (this row)
            float gn = 1.0f, gd = 1.0f;          // high part (next row)
            const float e[4] = { v[j].x, v[j].y, v[j].z, v[j].w };
#pragma unroll
            for (int c = 0; c < 4; ++c) {
                const int   k  = j + c;
                const float a  = e[c] * e[c];
                const float tn = fmaf(p0[k], a, pn[k]);  // wn + w0*x^2
                const float td = pn[k] + a;              // wn + x^2
                if (c < s) { ln *= tn; ld *= td; }
                else       { gn *= tn; gd *= td; }
            }
            num[j] = hn * ln;
            den[j] = hd * ld;
            hn = gn; hd = gd;
        }

        // ---- 1 division per row (<=4 terms each: safe fp32 range) ----
        float rr[4];
#pragma unroll
        for (int r = 0; r < 4; ++r)
            rr[r] = __fdividef(num[r], den[r]);

        // ---- 32-lane product, 4 independent chains interleaved ----
#pragma unroll
        for (int o = 1; o <= 16; o <<= 1)
#pragma unroll
            for (int r = 0; r < 4; ++r)
                rr[r] *= __shfl_xor_sync(0xFFFFFFFFu, rr[r], o);

        if (lane == 0) {
            float4 o4;
            o4.x = W2ALL * rr[0];
            o4.y = W2ALL * rr[1];
            o4.z = W2ALL * rr[2];
            o4.w = W2ALL * rr[3];
            *reinterpret_cast<float4*>(out + grp * 4) = o4;
        }
    }
}

extern "C" void kernel_launch(void* const* d_in, const int* in_sizes, int n_in,
                              void* d_out, int out_size)
{
    const float* x = (const float*)d_in[0];   // (B, G) fp32
    const float* w = (const float*)d_in[1];   // (G, 3) fp32
    float* out = (float*)d_out;               // (B, 1) fp32

    const int rows    = in_sizes[0] / GG;     // 524288
    const int ngroups = rows / 4;             // 131072

    const int threads = 256;
    const int blocks  = 2048;                 // 16384 warps -> 8 groups each
    hill_f4s_kernel<<<blocks, threads>>>(x, w, out, ngroups);
}